// round 5
// baseline (speedup 1.0000x reference)
#include <cuda_runtime.h>
#include <cstdint>

#define NB 512
#define NN 128
#define ND 256
#define NTH 512
#define PS 132   // SshT pitch: 132 % 32 == 4  -> A-frag bank = 4g+tg (distinct)
#define PA 136   // adj/X pitch: 136 % 32 == 8 -> B-frag bank = 8tg+g (distinct)
#define PT 132   // T1 pitch (reuses adj buffer)

static __device__ __forceinline__ float tf32r(float f){
    uint32_t r;
    asm("cvt.rna.tf32.f32 %0, %1;" : "=r"(r) : "f"(f));
    return __uint_as_float(r);
}

#define MMA8(C, A, B0, B1) \
    asm volatile("mma.sync.aligned.m16n8k8.row.col.f32.tf32.tf32.f32 " \
        "{%0,%1,%2,%3}, {%4,%5,%6,%7}, {%8,%9}, {%0,%1,%2,%3};" \
        : "+f"((C)[0]), "+f"((C)[1]), "+f"((C)[2]), "+f"((C)[3]) \
        : "r"((A)[0]), "r"((A)[1]), "r"((A)[2]), "r"((A)[3]), "r"(B0), "r"(B1))

// One 16x32 warp tile of C = A(16xK) * B(Kx32), K=128, software-pipelined.
// BT=0: B stored row-major [m][j] pitch pb; BT=1: B stored [j][m] pitch pb.
template<int BT>
static __device__ __forceinline__ void gemm_tile(
    float (&acc)[4][4], const uint32_t* __restrict__ Amat, int pa_,
    const uint32_t* __restrict__ Bmat, int pb_,
    int i0, int j0, int g, int tg)
{
    uint32_t a[4], bf[4][2];
    const int r0 = i0 + g;
    // prefetch k-step 0
    {
        const int m0 = 0;
        a[0] = Amat[r0 * pa_ + m0 + tg];
        a[1] = Amat[(r0 + 8) * pa_ + m0 + tg];
        a[2] = Amat[r0 * pa_ + m0 + tg + 4];
        a[3] = Amat[(r0 + 8) * pa_ + m0 + tg + 4];
        #pragma unroll
        for (int jt = 0; jt < 4; ++jt){
            int j = j0 + jt * 8 + g;
            bf[jt][0] = BT ? Bmat[j * pb_ + m0 + tg]     : Bmat[(m0 + tg) * pb_ + j];
            bf[jt][1] = BT ? Bmat[j * pb_ + m0 + tg + 4] : Bmat[(m0 + tg + 4) * pb_ + j];
        }
    }
    #pragma unroll
    for (int ks = 0; ks < 16; ++ks){
        uint32_t an[4], bn[4][2];
        if (ks < 15){
            const int m0 = (ks + 1) * 8;
            an[0] = Amat[r0 * pa_ + m0 + tg];
            an[1] = Amat[(r0 + 8) * pa_ + m0 + tg];
            an[2] = Amat[r0 * pa_ + m0 + tg + 4];
            an[3] = Amat[(r0 + 8) * pa_ + m0 + tg + 4];
            #pragma unroll
            for (int jt = 0; jt < 4; ++jt){
                int j = j0 + jt * 8 + g;
                bn[jt][0] = BT ? Bmat[j * pb_ + m0 + tg]     : Bmat[(m0 + tg) * pb_ + j];
                bn[jt][1] = BT ? Bmat[j * pb_ + m0 + tg + 4] : Bmat[(m0 + tg + 4) * pb_ + j];
            }
        }
        #pragma unroll
        for (int jt = 0; jt < 4; ++jt)
            MMA8(acc[jt], a, bf[jt][0], bf[jt][1]);
        if (ks < 15){
            #pragma unroll
            for (int q = 0; q < 4; ++q) a[q] = an[q];
            #pragma unroll
            for (int jt = 0; jt < 4; ++jt){ bf[jt][0] = bn[jt][0]; bf[jt][1] = bn[jt][1]; }
        }
    }
}

__global__ __launch_bounds__(1024, 1) void kmain(
    const float* __restrict__ x, const float* __restrict__ adj,
    const int* __restrict__ head, const float* __restrict__ lw,
    const float* __restrict__ bias, float* __restrict__ emb, float* __restrict__ nadj)
{
    extern __shared__ float sm[];
    float* Ssh = sm;               // SshT[j][m] = S[m][j], tf32, pitch PS
    float* AB  = sm + NN * PS;     // adj fp32 (pitch PA) -> later T1 tf32 (pitch PT)
    float* XB  = AB + NN * PA;     // X tile [128][128], tf32, pitch PA

    __shared__ float sh_w[ND];
    __shared__ float sh_dinv[NN], sh_coef[NN], sh_dv[NN], sh_alpha[NN], sh_ca[NN];
    __shared__ int   sh_flags[NN];
    __shared__ float sh_cut;

    const int b = blockIdx.x, tid = threadIdx.x;
    const int lane = tid & 31, wid = tid >> 5;
    const int g = lane >> 2, tg = lane & 3;      // mma fragment coords
    const int i0 = (wid >> 2) * 16;              // warp rows (8 blocks of 16)
    const int j0 = (wid & 3) * 32;               // warp cols (4 blocks of 32)

    const float* xb = x + (size_t)b * NN * ND;
    const float* ab = adj + (size_t)b * NN * NN;

    // ---- loads: adj (fp32), X tile 0 (tf32), weights, flag init ----
    for (int u = tid; u < NN * NN; u += 1024) AB[(u >> 7) * PA + (u & 127)] = ab[u];
    for (int u = tid; u < NN * 128; u += 1024){
        int m = u >> 7, d = u & 127;
        XB[m * PA + d] = tf32r(xb[m * ND + d]);
    }
    if (tid < ND) sh_w[tid] = lw[tid];
    if (tid < NN) sh_flags[tid] = 0;
    if (tid == 0) sh_cut = 0.f;
    __syncthreads();

    // unique-head marking (idempotent racy writes)
    if (tid < NTH) sh_flags[head[(size_t)b * NTH + tid] & (NN - 1)] = 1;

    // ---- rowsum_r, v_r = x[r]·w ----
    for (int r = wid; r < NN; r += 32){
        float s = 0.f, rs = 0.f;
        #pragma unroll
        for (int q = 0; q < 8; ++q) s += xb[r * ND + lane + q * 32] * sh_w[lane + q * 32];
        #pragma unroll
        for (int q = 0; q < 4; ++q) rs += AB[r * PA + lane + q * 32];
        #pragma unroll
        for (int o = 16; o; o >>= 1){
            s  += __shfl_down_sync(~0u, s, o);
            rs += __shfl_down_sync(~0u, rs, o);
        }
        if (!lane){
            float di = rsqrtf(fmaxf(rs + 1.f, 1.f));
            sh_dinv[r] = di;
            sh_coef[r] = (rs > 0.f) ? di : 0.f;
            sh_dv[r]   = di * s;
        }
    }
    __syncthreads();

    // ---- alpha_r = sigmoid((coef_r*(adj[r]·dv + dv_r) + bias)^2) ----
    const float bia = bias[0];
    for (int r = wid; r < NN; r += 32){
        float t = 0.f;
        #pragma unroll
        for (int q = 0; q < 4; ++q){
            int m = lane + q * 32;
            t += AB[r * PA + m] * sh_dv[m];
        }
        #pragma unroll
        for (int o = 16; o; o >>= 1) t += __shfl_down_sync(~0u, t, o);
        if (!lane){
            t += sh_dv[r];
            float o1 = sh_coef[r] * t + bia;
            sh_alpha[r] = 1.f / (1.f + __expf(-(o1 * o1)));
        }
    }
    const int nuniq = __syncthreads_count((tid < NN) ? sh_flags[tid] : 0);

    // ---- cut = k-th largest alpha (tie-correct) ----
    if (nuniq > 1 && tid < NN){
        float a = sh_alpha[tid];
        int gt = 0, ge = 0;
        for (int j2 = 0; j2 < NN; ++j2){
            float aj = sh_alpha[j2];
            gt += (aj > a); ge += (aj >= a);
        }
        int k   = (nuniq + 9) / 10 + 1;
        int idx = min(k - 1, NN - 1);
        if (gt <= idx && idx < ge) sh_cut = a;
    }
    __syncthreads();
    if (tid < NN) sh_ca[tid] = fmaxf(sh_alpha[tid] + 1e-7f - sh_cut, 0.f);
    __syncthreads();

    // ---- SshT[j][r] = S[r][j] (row-r L1-normalized), tf32-rounded ----
    for (int r = wid; r < NN; r += 32){
        float c = sh_coef[r];
        float vals[4], ssum = 0.f;
        #pragma unroll
        for (int q = 0; q < 4; ++q){
            int j = lane + q * 32;
            float a = AB[r * PA + j] + ((j == r) ? 1.f : 0.f);
            float v = c * a * sh_dinv[j] * sh_ca[j];
            vals[q] = v; ssum += v;   // all terms nonneg
        }
        #pragma unroll
        for (int o = 16; o; o >>= 1) ssum += __shfl_xor_sync(~0u, ssum, o);
        float inv = 1.f / fmaxf(ssum, 1e-12f);
        #pragma unroll
        for (int q = 0; q < 4; ++q)
            Ssh[(lane + q * 32) * PS + r] = tf32r(vals[q] * inv);
    }
    __syncthreads();

    // ---- round adj to tf32 in place ----
    for (int u = tid; u < NN * NN; u += 1024){
        int idx = (u >> 7) * PA + (u & 127);
        AB[idx] = tf32r(AB[idx]);
    }
    __syncthreads();

    const uint32_t* Su = (const uint32_t*)Ssh;
    const uint32_t* Au = (const uint32_t*)AB;
    const uint32_t* Xu = (const uint32_t*)XB;

    // =========== GEMM1: T1 = S^T @ adj ===========
    float c1[4][4];
    #pragma unroll
    for (int jt = 0; jt < 4; ++jt)
        #pragma unroll
        for (int q = 0; q < 4; ++q) c1[jt][q] = 0.f;
    gemm_tile<0>(c1, Su, PS, Au, PA, i0, j0, g, tg);
    __syncthreads();   // all GEMM1 reads of adj done

    // ---- store T1 (tf32) into the adj buffer, pitch PT ----
    float* T1 = AB;
    #pragma unroll
    for (int jt = 0; jt < 4; ++jt){
        int r0 = i0 + g, col = j0 + jt * 8 + 2 * tg;
        *(float2*)(T1 + r0 * PT + col) =
            make_float2(tf32r(c1[jt][0]), tf32r(c1[jt][1]));
        *(float2*)(T1 + (r0 + 8) * PT + col) =
            make_float2(tf32r(c1[jt][2]), tf32r(c1[jt][3]));
    }
    __syncthreads();

    // =========== GEMM3: nadj = T1 @ S (B[m][j] = SshT[j][m]) ===========
    {
        float c3[4][4];
        #pragma unroll
        for (int jt = 0; jt < 4; ++jt)
            #pragma unroll
            for (int q = 0; q < 4; ++q) c3[jt][q] = 0.f;
        gemm_tile<1>(c3, (const uint32_t*)T1, PT, Su, PS, i0, j0, g, tg);
        float* nb = nadj + (size_t)b * NN * NN;
        #pragma unroll
        for (int jt = 0; jt < 4; ++jt){
            int r0 = i0 + g, col = j0 + jt * 8 + 2 * tg;
            *(float2*)(nb + r0 * NN + col)       = make_float2(c3[jt][0], c3[jt][1]);
            *(float2*)(nb + (r0 + 8) * NN + col) = make_float2(c3[jt][2], c3[jt][3]);
        }
    }

    // =========== GEMM2: emb = S^T @ X, two 128-wide d-tiles ===========
    #pragma unroll 1
    for (int t = 0; t < 2; ++t){
        if (t == 1){
            __syncthreads();   // tile-0 consumers done
            for (int u = tid; u < NN * 128; u += 1024){
                int m = u >> 7, d = u & 127;
                XB[m * PA + d] = tf32r(xb[m * ND + 128 + d]);
            }
            __syncthreads();
        }
        float c2[4][4];
        #pragma unroll
        for (int jt = 0; jt < 4; ++jt)
            #pragma unroll
            for (int q = 0; q < 4; ++q) c2[jt][q] = 0.f;
        gemm_tile<0>(c2, Su, PS, Xu, PA, i0, j0, g, tg);
        float* eb = emb + (size_t)b * NN * ND + t * 128;
        #pragma unroll
        for (int jt = 0; jt < 4; ++jt){
            int r0 = i0 + g, col = j0 + jt * 8 + 2 * tg;
            *(float2*)(eb + r0 * ND + col)       = make_float2(c2[jt][0], c2[jt][1]);
            *(float2*)(eb + (r0 + 8) * ND + col) = make_float2(c2[jt][2], c2[jt][3]);
        }
    }
}

extern "C" void kernel_launch(void* const* d_in, const int* in_sizes, int n_in,
                              void* d_out, int out_size) {
    const float* x    = (const float*)d_in[0];
    const float* adj  = (const float*)d_in[1];
    const int*   head = (const int*)d_in[2];
    const float* lw   = (const float*)d_in[3];
    const float* bias = (const float*)d_in[4];

    float* out  = (float*)d_out;
    float* emb  = out;                            // [B, N, D]
    float* nadj = out + (size_t)NB * NN * ND;     // [B, N, N]

    const int dsmem = (NN * PS + NN * PA + NN * PA) * 4;   // 206,848 B
    cudaFuncSetAttribute(kmain, cudaFuncAttributeMaxDynamicSharedMemorySize, dsmem);
    kmain<<<NB, 1024, dsmem>>>(x, adj, head, lw, bias, emb, nadj);
}

// round 6
// speedup vs baseline: 1.0806x; 1.0806x over previous
#include <cuda_runtime.h>
#include <cstdint>

#define NB 512
#define NN 128
#define ND 256
#define NTH 512
#define PS 132   // SshT pitch: 132 % 32 == 4  -> frag bank = 4g+tg (distinct)
#define PA 136   // adj/X pitch: 136 % 32 == 8 -> frag bank = 8tg+g (distinct)
#define PT 132   // T1 pitch (reuses adj buffer)

static __device__ __forceinline__ float tf32r(float f){
    uint32_t r;
    asm("cvt.rna.tf32.f32 %0, %1;" : "=r"(r) : "f"(f));
    return __uint_as_float(r);
}

#define MMA8(C, A, B0, B1) \
    asm volatile("mma.sync.aligned.m16n8k8.row.col.f32.tf32.tf32.f32 " \
        "{%0,%1,%2,%3}, {%4,%5,%6,%7}, {%8,%9}, {%0,%1,%2,%3};" \
        : "+f"((C)[0]), "+f"((C)[1]), "+f"((C)[2]), "+f"((C)[3]) \
        : "r"((A)[0]), "r"((A)[1]), "r"((A)[2]), "r"((A)[3]), "r"(B0), "r"(B1))

__global__ __launch_bounds__(512, 1) void kmain(
    const float* __restrict__ x, const float* __restrict__ adj,
    const int* __restrict__ head, const float* __restrict__ lw,
    const float* __restrict__ bias, float* __restrict__ emb, float* __restrict__ nadj)
{
    extern __shared__ float sm[];
    float* Ssh = sm;               // SshT[j][m] = S[m][j], tf32, pitch PS
    float* AB  = sm + NN * PS;     // adj fp32 (pitch PA) -> later T1 tf32 (pitch PT)
    float* XB  = AB + NN * PA;     // X tile [128][128], tf32, pitch PA

    __shared__ float sh_w[ND];
    __shared__ float sh_dinv[NN], sh_coef[NN], sh_dv[NN], sh_alpha[NN], sh_ca[NN];
    __shared__ int   sh_flags[NN];
    __shared__ float sh_cut;

    const int b = blockIdx.x, tid = threadIdx.x;
    const int lane = tid & 31, wid = tid >> 5;
    const int g = lane >> 2, tg = lane & 3;      // mma fragment coords
    const int i0 = (wid >> 2) * 32;              // warp rows
    const int j0 = (wid & 3) * 32;               // warp cols

    const float* xb = x + (size_t)b * NN * ND;
    const float* ab = adj + (size_t)b * NN * NN;

    // ---- loads: adj (fp32), X tile 0 (tf32), weights, flag init ----
    for (int u = tid; u < NN * NN; u += 512) AB[(u >> 7) * PA + (u & 127)] = ab[u];
    for (int u = tid; u < NN * 128; u += 512){
        int m = u >> 7, d = u & 127;
        XB[m * PA + d] = tf32r(xb[m * ND + d]);
    }
    if (tid < ND) sh_w[tid] = lw[tid];
    if (tid < NN) sh_flags[tid] = 0;
    if (tid == 0) sh_cut = 0.f;
    __syncthreads();

    // unique-head marking (idempotent racy writes)
    sh_flags[head[(size_t)b * NTH + tid] & (NN - 1)] = 1;

    // ---- rowsum_r, v_r = x[r]·w ----
    for (int r = wid; r < NN; r += 16){
        float s = 0.f, rs = 0.f;
        #pragma unroll
        for (int q = 0; q < 8; ++q) s += xb[r * ND + lane + q * 32] * sh_w[lane + q * 32];
        #pragma unroll
        for (int q = 0; q < 4; ++q) rs += AB[r * PA + lane + q * 32];
        #pragma unroll
        for (int o = 16; o; o >>= 1){
            s  += __shfl_down_sync(~0u, s, o);
            rs += __shfl_down_sync(~0u, rs, o);
        }
        if (!lane){
            float di = rsqrtf(fmaxf(rs + 1.f, 1.f));
            sh_dinv[r] = di;
            sh_coef[r] = (rs > 0.f) ? di : 0.f;
            sh_dv[r]   = di * s;
        }
    }
    __syncthreads();

    // ---- alpha_r = sigmoid((coef_r*(adj[r]·dv + dv_r) + bias)^2) ----
    const float bia = bias[0];
    for (int r = wid; r < NN; r += 16){
        float t = 0.f;
        #pragma unroll
        for (int q = 0; q < 4; ++q){
            int m = lane + q * 32;
            t += AB[r * PA + m] * sh_dv[m];
        }
        #pragma unroll
        for (int o = 16; o; o >>= 1) t += __shfl_down_sync(~0u, t, o);
        if (!lane){
            t += sh_dv[r];
            float o1 = sh_coef[r] * t + bia;
            sh_alpha[r] = 1.f / (1.f + __expf(-(o1 * o1)));
        }
    }
    const int nuniq = __syncthreads_count((tid < NN) ? sh_flags[tid] : 0);

    // ---- cut = k-th largest alpha (tie-correct) ----
    if (nuniq > 1 && tid < NN){
        float a = sh_alpha[tid];
        int gt = 0, ge = 0;
        for (int j2 = 0; j2 < NN; ++j2){
            float aj = sh_alpha[j2];
            gt += (aj > a); ge += (aj >= a);
        }
        int k   = (nuniq + 9) / 10 + 1;
        int idx = min(k - 1, NN - 1);
        if (gt <= idx && idx < ge) sh_cut = a;
    }
    __syncthreads();
    if (tid < NN) sh_ca[tid] = fmaxf(sh_alpha[tid] + 1e-7f - sh_cut, 0.f);
    __syncthreads();

    // ---- SshT[j][r] = S[r][j] (row-r L1-normalized), tf32-rounded ----
    for (int r = wid; r < NN; r += 16){
        float c = sh_coef[r];
        float vals[4], ssum = 0.f;
        #pragma unroll
        for (int q = 0; q < 4; ++q){
            int j = lane + q * 32;
            float a = AB[r * PA + j] + ((j == r) ? 1.f : 0.f);
            float v = c * a * sh_dinv[j] * sh_ca[j];
            vals[q] = v; ssum += v;   // all terms nonneg
        }
        #pragma unroll
        for (int o = 16; o; o >>= 1) ssum += __shfl_xor_sync(~0u, ssum, o);
        float inv = 1.f / fmaxf(ssum, 1e-12f);
        #pragma unroll
        for (int q = 0; q < 4; ++q)
            Ssh[(lane + q * 32) * PS + r] = tf32r(vals[q] * inv);
    }
    __syncthreads();

    // ---- round adj to tf32 in place ----
    for (int u = tid; u < NN * NN; u += 512){
        int idx = (u >> 7) * PA + (u & 127);
        AB[idx] = tf32r(AB[idx]);
    }
    __syncthreads();

    const uint32_t* Su = (const uint32_t*)Ssh;
    const uint32_t* Au = (const uint32_t*)AB;
    const uint32_t* Xu = (const uint32_t*)XB;

    // ====== Phase A: GEMM1 (T1 = S^T adj) + GEMM2t0 (emb0 = S^T X0),
    //        SAME A operand — one A-frag load feeds both B streams. ======
    float cA[2][4][4], cX[2][4][4];
    #pragma unroll
    for (int s = 0; s < 2; ++s)
        #pragma unroll
        for (int jt = 0; jt < 4; ++jt)
            #pragma unroll
            for (int q = 0; q < 4; ++q){ cA[s][jt][q] = 0.f; cX[s][jt][q] = 0.f; }

    for (int ks = 0; ks < 16; ++ks){
        int m0 = ks * 8;
        uint32_t a[2][4];
        #pragma unroll
        for (int s = 0; s < 2; ++s){
            int r0 = i0 + s * 16 + g;
            a[s][0] = Su[r0 * PS + m0 + tg];
            a[s][1] = Su[(r0 + 8) * PS + m0 + tg];
            a[s][2] = Su[r0 * PS + m0 + tg + 4];
            a[s][3] = Su[(r0 + 8) * PS + m0 + tg + 4];
        }
        #pragma unroll
        for (int jt = 0; jt < 4; ++jt){
            int j = j0 + jt * 8 + g;
            uint32_t b0 = Au[(m0 + tg) * PA + j];
            uint32_t b1 = Au[(m0 + tg + 4) * PA + j];
            uint32_t x0 = Xu[(m0 + tg) * PA + j];
            uint32_t x1 = Xu[(m0 + tg + 4) * PA + j];
            MMA8(cA[0][jt], a[0], b0, b1);
            MMA8(cX[0][jt], a[0], x0, x1);
            MMA8(cA[1][jt], a[1], b0, b1);
            MMA8(cX[1][jt], a[1], x0, x1);
        }
    }
    __syncthreads();   // phase A reads of AB/XB done

    // ---- store T1 (tf32) into adj buffer; emb tile 0 to gmem; load X1 ----
    float* T1 = AB;
    #pragma unroll
    for (int s = 0; s < 2; ++s)
        #pragma unroll
        for (int jt = 0; jt < 4; ++jt){
            int r0 = i0 + s * 16 + g, col = j0 + jt * 8 + 2 * tg;
            *(float2*)(T1 + r0 * PT + col) =
                make_float2(tf32r(cA[s][jt][0]), tf32r(cA[s][jt][1]));
            *(float2*)(T1 + (r0 + 8) * PT + col) =
                make_float2(tf32r(cA[s][jt][2]), tf32r(cA[s][jt][3]));
        }
    {
        float* eb = emb + (size_t)b * NN * ND;
        #pragma unroll
        for (int s = 0; s < 2; ++s)
            #pragma unroll
            for (int jt = 0; jt < 4; ++jt){
                int r0 = i0 + s * 16 + g, col = j0 + jt * 8 + 2 * tg;
                *(float2*)(eb + r0 * ND + col)       = make_float2(cX[s][jt][0], cX[s][jt][1]);
                *(float2*)(eb + (r0 + 8) * ND + col) = make_float2(cX[s][jt][2], cX[s][jt][3]);
            }
    }
    for (int u = tid; u < NN * 128; u += 512){
        int m = u >> 7, d = u & 127;
        XB[m * PA + d] = tf32r(xb[m * ND + 128 + d]);
    }
    __syncthreads();

    // ====== Phase B: GEMM3 (nadj = T1 S) + GEMM2t1 (emb1 = S^T X1) ======
    const uint32_t* Tu = (const uint32_t*)T1;
    #pragma unroll
    for (int s = 0; s < 2; ++s)
        #pragma unroll
        for (int jt = 0; jt < 4; ++jt)
            #pragma unroll
            for (int q = 0; q < 4; ++q){ cA[s][jt][q] = 0.f; cX[s][jt][q] = 0.f; }

    for (int ks = 0; ks < 16; ++ks){
        int m0 = ks * 8;
        uint32_t a3[2][4], a2[2][4];
        #pragma unroll
        for (int s = 0; s < 2; ++s){
            int r0 = i0 + s * 16 + g;
            a3[s][0] = Tu[r0 * PT + m0 + tg];
            a3[s][1] = Tu[(r0 + 8) * PT + m0 + tg];
            a3[s][2] = Tu[r0 * PT + m0 + tg + 4];
            a3[s][3] = Tu[(r0 + 8) * PT + m0 + tg + 4];
            a2[s][0] = Su[r0 * PS + m0 + tg];
            a2[s][1] = Su[(r0 + 8) * PS + m0 + tg];
            a2[s][2] = Su[r0 * PS + m0 + tg + 4];
            a2[s][3] = Su[(r0 + 8) * PS + m0 + tg + 4];
        }
        #pragma unroll
        for (int jt = 0; jt < 4; ++jt){
            int j = j0 + jt * 8 + g;
            uint32_t b0 = Su[j * PS + m0 + tg];        // S[m][j] = SshT[j][m]
            uint32_t b1 = Su[j * PS + m0 + tg + 4];
            uint32_t x0 = Xu[(m0 + tg) * PA + j];
            uint32_t x1 = Xu[(m0 + tg + 4) * PA + j];
            MMA8(cA[0][jt], a3[0], b0, b1);
            MMA8(cX[0][jt], a2[0], x0, x1);
            MMA8(cA[1][jt], a3[1], b0, b1);
            MMA8(cX[1][jt], a2[1], x0, x1);
        }
    }

    // ---- epilogues: nadj, emb tile 1 ----
    {
        float* nb = nadj + (size_t)b * NN * NN;
        float* eb = emb + (size_t)b * NN * ND + 128;
        #pragma unroll
        for (int s = 0; s < 2; ++s)
            #pragma unroll
            for (int jt = 0; jt < 4; ++jt){
                int r0 = i0 + s * 16 + g, col = j0 + jt * 8 + 2 * tg;
                *(float2*)(nb + r0 * NN + col)       = make_float2(cA[s][jt][0], cA[s][jt][1]);
                *(float2*)(nb + (r0 + 8) * NN + col) = make_float2(cA[s][jt][2], cA[s][jt][3]);
                *(float2*)(eb + r0 * ND + col)       = make_float2(cX[s][jt][0], cX[s][jt][1]);
                *(float2*)(eb + (r0 + 8) * ND + col) = make_float2(cX[s][jt][2], cX[s][jt][3]);
            }
    }
}

extern "C" void kernel_launch(void* const* d_in, const int* in_sizes, int n_in,
                              void* d_out, int out_size) {
    const float* x    = (const float*)d_in[0];
    const float* adj  = (const float*)d_in[1];
    const int*   head = (const int*)d_in[2];
    const float* lw   = (const float*)d_in[3];
    const float* bias = (const float*)d_in[4];

    float* out  = (float*)d_out;
    float* emb  = out;                            // [B, N, D]
    float* nadj = out + (size_t)NB * NN * ND;     // [B, N, N]

    const int dsmem = (NN * PS + NN * PA + NN * PA) * 4;   // 206,848 B
    cudaFuncSetAttribute(kmain, cudaFuncAttributeMaxDynamicSharedMemorySize, dsmem);
    kmain<<<NB, 512, dsmem>>>(x, adj, head, lw, bias, emb, nadj);
}

// round 7
// speedup vs baseline: 1.1190x; 1.0356x over previous
#include <cuda_runtime.h>
#include <cstdint>

#define NB 512
#define NN 128
#define ND 256
#define NTH 512
#define PS 132   // SshT pitch: 132 % 32 == 4  -> frag bank = 4g+tg (distinct)
#define PA 136   // adj/X pitch: 136 % 32 == 8 -> frag bank = 8tg+g (distinct)
#define PT 132   // T1 pitch (reuses adj buffer)

static __device__ __forceinline__ float tf32r(float f){
    uint32_t r;
    asm("cvt.rna.tf32.f32 %0, %1;" : "=r"(r) : "f"(f));
    return __uint_as_float(r);
}

#define MMA8(C, A, B0, B1) \
    asm volatile("mma.sync.aligned.m16n8k8.row.col.f32.tf32.tf32.f32 " \
        "{%0,%1,%2,%3}, {%4,%5,%6,%7}, {%8,%9}, {%0,%1,%2,%3};" \
        : "+f"((C)[0]), "+f"((C)[1]), "+f"((C)[2]), "+f"((C)[3]) \
        : "r"((A)[0]), "r"((A)[1]), "r"((A)[2]), "r"((A)[3]), "r"(B0), "r"(B1))

__global__ __launch_bounds__(512, 1) void kmain(
    const float* __restrict__ x, const float* __restrict__ adj,
    const int* __restrict__ head, const float* __restrict__ lw,
    const float* __restrict__ bias, float* __restrict__ emb, float* __restrict__ nadj)
{
    extern __shared__ float sm[];
    float* Ssh = sm;               // SshT[j][m] = S[m][j], tf32, pitch PS
    float* AB  = sm + NN * PS;     // adj fp32 (pitch PA) -> later T1 tf32 (pitch PT)
    float* XB  = AB + NN * PA;     // X tile [128][128], tf32, pitch PA

    __shared__ float sh_w[ND];
    __shared__ float sh_dinv[NN], sh_coef[NN], sh_dv[NN], sh_alpha[NN], sh_ca[NN];
    __shared__ int   sh_flags[NN];
    __shared__ float sh_cut;

    const int b = blockIdx.x, tid = threadIdx.x;
    const int lane = tid & 31, wid = tid >> 5;
    const int g = lane >> 2, tg = lane & 3;      // mma fragment coords
    const int i0 = (wid >> 2) * 32;              // warp rows
    const int j0 = (wid & 3) * 32;               // warp cols

    const float* xb = x + (size_t)b * NN * ND;
    const float* ab = adj + (size_t)b * NN * NN;

    // ---- loads: adj (fp32), X tile 0 (tf32), weights, flag init ----
    for (int u = tid; u < NN * NN; u += 512) AB[(u >> 7) * PA + (u & 127)] = ab[u];
    for (int u = tid; u < NN * 128; u += 512){
        int m = u >> 7, d = u & 127;
        XB[m * PA + d] = tf32r(xb[m * ND + d]);
    }
    if (tid < ND) sh_w[tid] = lw[tid];
    if (tid < NN) sh_flags[tid] = 0;
    if (tid == 0) sh_cut = 0.f;
    __syncthreads();

    // unique-head marking (idempotent racy writes)
    sh_flags[head[(size_t)b * NTH + tid] & (NN - 1)] = 1;

    // ---- rowsum_r, v_r = x[r]·w ----
    for (int r = wid; r < NN; r += 16){
        float s = 0.f, rs = 0.f;
        #pragma unroll
        for (int q = 0; q < 8; ++q) s += xb[r * ND + lane + q * 32] * sh_w[lane + q * 32];
        #pragma unroll
        for (int q = 0; q < 4; ++q) rs += AB[r * PA + lane + q * 32];
        #pragma unroll
        for (int o = 16; o; o >>= 1){
            s  += __shfl_down_sync(~0u, s, o);
            rs += __shfl_down_sync(~0u, rs, o);
        }
        if (!lane){
            float di = rsqrtf(fmaxf(rs + 1.f, 1.f));
            sh_dinv[r] = di;
            sh_coef[r] = (rs > 0.f) ? di : 0.f;
            sh_dv[r]   = di * s;
        }
    }
    __syncthreads();

    // ---- alpha_r = sigmoid((coef_r*(adj[r]·dv + dv_r) + bias)^2) ----
    const float bia = bias[0];
    for (int r = wid; r < NN; r += 16){
        float t = 0.f;
        #pragma unroll
        for (int q = 0; q < 4; ++q){
            int m = lane + q * 32;
            t += AB[r * PA + m] * sh_dv[m];
        }
        #pragma unroll
        for (int o = 16; o; o >>= 1) t += __shfl_down_sync(~0u, t, o);
        if (!lane){
            t += sh_dv[r];
            float o1 = sh_coef[r] * t + bia;
            sh_alpha[r] = 1.f / (1.f + __expf(-(o1 * o1)));
        }
    }
    const int nuniq = __syncthreads_count((tid < NN) ? sh_flags[tid] : 0);

    // ---- cut = k-th largest alpha (tie-correct) ----
    if (nuniq > 1 && tid < NN){
        float a = sh_alpha[tid];
        int gt = 0, ge = 0;
        for (int j2 = 0; j2 < NN; ++j2){
            float aj = sh_alpha[j2];
            gt += (aj > a); ge += (aj >= a);
        }
        int k   = (nuniq + 9) / 10 + 1;
        int idx = min(k - 1, NN - 1);
        if (gt <= idx && idx < ge) sh_cut = a;
    }
    __syncthreads();
    if (tid < NN) sh_ca[tid] = fmaxf(sh_alpha[tid] + 1e-7f - sh_cut, 0.f);
    __syncthreads();

    // ---- SshT[j][r] = S[r][j] (row-r L1-normalized), tf32-rounded ----
    for (int r = wid; r < NN; r += 16){
        float c = sh_coef[r];
        float vals[4], ssum = 0.f;
        #pragma unroll
        for (int q = 0; q < 4; ++q){
            int j = lane + q * 32;
            float a = AB[r * PA + j] + ((j == r) ? 1.f : 0.f);
            float v = c * a * sh_dinv[j] * sh_ca[j];
            vals[q] = v; ssum += v;   // all terms nonneg
        }
        #pragma unroll
        for (int o = 16; o; o >>= 1) ssum += __shfl_xor_sync(~0u, ssum, o);
        float inv = 1.f / fmaxf(ssum, 1e-12f);
        #pragma unroll
        for (int q = 0; q < 4; ++q)
            Ssh[(lane + q * 32) * PS + r] = tf32r(vals[q] * inv);
    }
    __syncthreads();

    // ---- round adj to tf32 in place ----
    for (int u = tid; u < NN * NN; u += 512){
        int idx = (u >> 7) * PA + (u & 127);
        AB[idx] = tf32r(AB[idx]);
    }
    __syncthreads();

    const uint32_t* Su = (const uint32_t*)Ssh;
    const uint32_t* Au = (const uint32_t*)AB;
    const uint32_t* Xu = (const uint32_t*)XB;

    // ====== Phase A: GEMM1 (T1 = S^T adj) + GEMM2t0 (emb0 = S^T X0),
    //        SAME A operand — one A-frag load feeds both B streams. ======
    float cA[2][4][4], cX[2][4][4];
    #pragma unroll
    for (int s = 0; s < 2; ++s)
        #pragma unroll
        for (int jt = 0; jt < 4; ++jt)
            #pragma unroll
            for (int q = 0; q < 4; ++q){ cA[s][jt][q] = 0.f; cX[s][jt][q] = 0.f; }

    for (int ks = 0; ks < 16; ++ks){
        int m0 = ks * 8;
        uint32_t a[2][4];
        #pragma unroll
        for (int s = 0; s < 2; ++s){
            int r0 = i0 + s * 16 + g;
            a[s][0] = Su[r0 * PS + m0 + tg];
            a[s][1] = Su[(r0 + 8) * PS + m0 + tg];
            a[s][2] = Su[r0 * PS + m0 + tg + 4];
            a[s][3] = Su[(r0 + 8) * PS + m0 + tg + 4];
        }
        #pragma unroll
        for (int jt = 0; jt < 4; ++jt){
            int j = j0 + jt * 8 + g;
            uint32_t b0 = Au[(m0 + tg) * PA + j];
            uint32_t b1 = Au[(m0 + tg + 4) * PA + j];
            uint32_t x0 = Xu[(m0 + tg) * PA + j];
            uint32_t x1 = Xu[(m0 + tg + 4) * PA + j];
            MMA8(cA[0][jt], a[0], b0, b1);
            MMA8(cX[0][jt], a[0], x0, x1);
            MMA8(cA[1][jt], a[1], b0, b1);
            MMA8(cX[1][jt], a[1], x0, x1);
        }
    }
    __syncthreads();   // phase A reads of AB/XB done

    // ---- store T1 (tf32) into adj buffer; emb tile 0 to gmem; load X1 ----
    float* T1 = AB;
    #pragma unroll
    for (int s = 0; s < 2; ++s)
        #pragma unroll
        for (int jt = 0; jt < 4; ++jt){
            int r0 = i0 + s * 16 + g, col = j0 + jt * 8 + 2 * tg;
            *(float2*)(T1 + r0 * PT + col) =
                make_float2(tf32r(cA[s][jt][0]), tf32r(cA[s][jt][1]));
            *(float2*)(T1 + (r0 + 8) * PT + col) =
                make_float2(tf32r(cA[s][jt][2]), tf32r(cA[s][jt][3]));
        }
    {
        float* eb = emb + (size_t)b * NN * ND;
        #pragma unroll
        for (int s = 0; s < 2; ++s)
            #pragma unroll
            for (int jt = 0; jt < 4; ++jt){
                int r0 = i0 + s * 16 + g, col = j0 + jt * 8 + 2 * tg;
                *(float2*)(eb + r0 * ND + col)       = make_float2(cX[s][jt][0], cX[s][jt][1]);
                *(float2*)(eb + (r0 + 8) * ND + col) = make_float2(cX[s][jt][2], cX[s][jt][3]);
            }
    }
    for (int u = tid; u < NN * 128; u += 512){
        int m = u >> 7, d = u & 127;
        XB[m * PA + d] = tf32r(xb[m * ND + 128 + d]);
    }
    __syncthreads();

    // ====== Phase B: GEMM3 (nadj = T1 S) + GEMM2t1 (emb1 = S^T X1) ======
    const uint32_t* Tu = (const uint32_t*)T1;
    #pragma unroll
    for (int s = 0; s < 2; ++s)
        #pragma unroll
        for (int jt = 0; jt < 4; ++jt)
            #pragma unroll
            for (int q = 0; q < 4; ++q){ cA[s][jt][q] = 0.f; cX[s][jt][q] = 0.f; }

    for (int ks = 0; ks < 16; ++ks){
        int m0 = ks * 8;
        uint32_t a3[2][4], a2[2][4];
        #pragma unroll
        for (int s = 0; s < 2; ++s){
            int r0 = i0 + s * 16 + g;
            a3[s][0] = Tu[r0 * PT + m0 + tg];
            a3[s][1] = Tu[(r0 + 8) * PT + m0 + tg];
            a3[s][2] = Tu[r0 * PT + m0 + tg + 4];
            a3[s][3] = Tu[(r0 + 8) * PT + m0 + tg + 4];
            a2[s][0] = Su[r0 * PS + m0 + tg];
            a2[s][1] = Su[(r0 + 8) * PS + m0 + tg];
            a2[s][2] = Su[r0 * PS + m0 + tg + 4];
            a2[s][3] = Su[(r0 + 8) * PS + m0 + tg + 4];
        }
        #pragma unroll
        for (int jt = 0; jt < 4; ++jt){
            int j = j0 + jt * 8 + g;
            uint32_t b0 = Su[j * PS + m0 + tg];        // S[m][j] = SshT[j][m]
            uint32_t b1 = Su[j * PS + m0 + tg + 4];
            uint32_t x0 = Xu[(m0 + tg) * PA + j];
            uint32_t x1 = Xu[(m0 + tg + 4) * PA + j];
            MMA8(cA[0][jt], a3[0], b0, b1);
            MMA8(cX[0][jt], a2[0], x0, x1);
            MMA8(cA[1][jt], a3[1], b0, b1);
            MMA8(cX[1][jt], a2[1], x0, x1);
        }
    }

    // ---- epilogues: nadj, emb tile 1 ----
    {
        float* nb = nadj + (size_t)b * NN * NN;
        float* eb = emb + (size_t)b * NN * ND + 128;
        #pragma unroll
        for (int s = 0; s < 2; ++s)
            #pragma unroll
            for (int jt = 0; jt < 4; ++jt){
                int r0 = i0 + s * 16 + g, col = j0 + jt * 8 + 2 * tg;
                *(float2*)(nb + r0 * NN + col)       = make_float2(cA[s][jt][0], cA[s][jt][1]);
                *(float2*)(nb + (r0 + 8) * NN + col) = make_float2(cA[s][jt][2], cA[s][jt][3]);
                *(float2*)(eb + r0 * ND + col)       = make_float2(cX[s][jt][0], cX[s][jt][1]);
                *(float2*)(eb + (r0 + 8) * ND + col) = make_float2(cX[s][jt][2], cX[s][jt][3]);
            }
    }
}

extern "C" void kernel_launch(void* const* d_in, const int* in_sizes, int n_in,
                              void* d_out, int out_size) {
    const float* x    = (const float*)d_in[0];
    const float* adj  = (const float*)d_in[1];
    const int*   head = (const int*)d_in[2];
    const float* lw   = (const float*)d_in[3];
    const float* bias = (const float*)d_in[4];

    float* out  = (float*)d_out;
    float* emb  = out;                            // [B, N, D]
    float* nadj = out + (size_t)NB * NN * ND;     // [B, N, N]

    const int dsmem = (NN * PS + NN * PA + NN * PA) * 4;   // 206,848 B
    cudaFuncSetAttribute(kmain, cudaFuncAttributeMaxDynamicSharedMemorySize, dsmem);
    kmain<<<NB, 512, dsmem>>>(x, adj, head, lw, bias, emb, nadj);
}

// round 8
// speedup vs baseline: 1.2323x; 1.1012x over previous
#include <cuda_runtime.h>
#include <cstdint>

#define NB 512
#define NN 128
#define ND 256
#define NTH 512

static __device__ __forceinline__ float tf32r(float f){
    uint32_t r;
    asm("cvt.rna.tf32.f32 %0, %1;" : "=r"(r) : "f"(f));
    return __uint_as_float(r);
}

#define MMA8S(C, A0,A1,A2,A3, B0, B1) \
    asm volatile("mma.sync.aligned.m16n8k8.row.col.f32.tf32.tf32.f32 " \
        "{%0,%1,%2,%3}, {%4,%5,%6,%7}, {%8,%9}, {%0,%1,%2,%3};" \
        : "+f"((C)[0]), "+f"((C)[1]), "+f"((C)[2]), "+f"((C)[3]) \
        : "r"(A0), "r"(A1), "r"(A2), "r"(A3), "r"(B0), "r"(B1))

// Fragment packs (per 128x128 operand): 2 arrays (lo/hi) of 2048 float4 chunks,
// chunk index = (blk*16 + ks)*32 + lane, lane = g*4 + tg.
// A-chunk (lo: s=0, hi: s=1): {A[i][m], A[i+8][m], A[i][m+4], A[i+8][m+4]},
//   i = ib*32 + s*16 + g, m = ks*8 + tg.
// B-chunk (lo: jt0/1, hi: jt2/3): {B[m][j], B[m+4][j], B[m][j+8], B[m+4][j+8]},
//   j = jb*32 + hf*16 + g, m = ks*8 + tg.

__global__ __launch_bounds__(512, 1) void kmain(
    const float* __restrict__ x, const float* __restrict__ adj,
    const int* __restrict__ head, const float* __restrict__ lw,
    const float* __restrict__ bias, float* __restrict__ emb, float* __restrict__ nadj)
{
    extern __shared__ float4 smq[];
    float4* SAl = smq;            // S^T as A (all GEMMs)       32 KB
    float4* SAh = smq + 2048;     //                             32 KB
    float4* B1l = smq + 4096;     // adj as B -> T1^T as B       32 KB
    float4* B1h = smq + 6144;     //                             32 KB
    float4* B2l = smq + 8192;     // X0 as B -> X1 as B          32 KB
    float4* B2h = smq + 10240;    //                             32 KB

    __shared__ float sh_w[ND];
    __shared__ float sh_dinv[NN], sh_coef[NN], sh_dv[NN], sh_alpha[NN], sh_ca[NN], sh_sc[NN];
    __shared__ int   sh_flags[NN];
    __shared__ float sh_cut;

    const int b = blockIdx.x, tid = threadIdx.x;
    const int lane = tid & 31, wid = tid >> 5;
    const int g = lane >> 2, tg = lane & 3;
    const int ibw = wid >> 2, jbw = wid & 3;
    const int i0 = ibw * 32, j0 = jbw * 32;

    const float* xb = x + (size_t)b * NN * ND;
    const float* ab = adj + (size_t)b * NN * NN;

    if (tid < ND) sh_w[tid] = lw[tid];
    if (tid < NN) sh_flags[tid] = 0;
    if (tid == 0) sh_cut = 0.f;
    __syncthreads();

    sh_flags[head[(size_t)b * NTH + tid] & (NN - 1)] = 1;

    // ---- rowsum_r, v_r = x[r]·w ----
    for (int r = wid; r < NN; r += 16){
        float s = 0.f, rs = 0.f;
        #pragma unroll
        for (int q = 0; q < 8; ++q) s += xb[r * ND + lane + q * 32] * sh_w[lane + q * 32];
        #pragma unroll
        for (int q = 0; q < 4; ++q) rs += ab[r * NN + lane + q * 32];
        #pragma unroll
        for (int o = 16; o; o >>= 1){
            s  += __shfl_down_sync(~0u, s, o);
            rs += __shfl_down_sync(~0u, rs, o);
        }
        if (!lane){
            float di = rsqrtf(fmaxf(rs + 1.f, 1.f));
            sh_dinv[r] = di;
            sh_coef[r] = (rs > 0.f) ? di : 0.f;
            sh_dv[r]   = di * s;
        }
    }
    __syncthreads();

    // ---- alpha_r = sigmoid((coef_r*(adj[r]·dv + dv_r) + bias)^2) ----
    const float bia = bias[0];
    for (int r = wid; r < NN; r += 16){
        float t = 0.f;
        #pragma unroll
        for (int q = 0; q < 4; ++q){
            int m = lane + q * 32;
            t += ab[r * NN + m] * sh_dv[m];
        }
        #pragma unroll
        for (int o = 16; o; o >>= 1) t += __shfl_down_sync(~0u, t, o);
        if (!lane){
            t += sh_dv[r];
            float o1 = sh_coef[r] * t + bia;
            sh_alpha[r] = 1.f / (1.f + __expf(-(o1 * o1)));
        }
    }
    const int nuniq = __syncthreads_count((tid < NN) ? sh_flags[tid] : 0);

    // ---- cut = k-th largest alpha (tie-correct) ----
    if (nuniq > 1 && tid < NN){
        float a = sh_alpha[tid];
        int gt = 0, ge = 0;
        for (int j2 = 0; j2 < NN; ++j2){
            float aj = sh_alpha[j2];
            gt += (aj > a); ge += (aj >= a);
        }
        int k   = (nuniq + 9) / 10 + 1;
        int idx = min(k - 1, NN - 1);
        if (gt <= idx && idx < ge) sh_cut = a;
    }
    __syncthreads();
    if (tid < NN) sh_ca[tid] = fmaxf(sh_alpha[tid] + 1e-7f - sh_cut, 0.f);
    __syncthreads();

    // ---- sc_m = coef_m / max(coef_m * sum_j (adj+I)_mj * dinv_j * ca_j, eps) ----
    for (int m = wid; m < NN; m += 16){
        float ss = 0.f;
        #pragma unroll
        for (int q = 0; q < 4; ++q){
            int j = lane + q * 32;
            float a = ab[m * NN + j] + ((j == m) ? 1.f : 0.f);
            ss += a * sh_dinv[j] * sh_ca[j];
        }
        #pragma unroll
        for (int o = 16; o; o >>= 1) ss += __shfl_down_sync(~0u, ss, o);
        if (!lane){
            float c = sh_coef[m];
            sh_sc[m] = c / fmaxf(c * ss, 1e-12f);
        }
    }
    __syncthreads();

    // ---- A-pack fill: S^T generated in fragment order ----
    for (int c = tid; c < 4096; c += 512){
        int ln = c & 31, ks = (c >> 5) & 15, ib = (c >> 9) & 3, s = c >> 11;
        int gp = ln >> 2, tp = ln & 3;
        int i = ib * 32 + s * 16 + gp, m = ks * 8 + tp;
        float fi  = sh_dinv[i] * sh_ca[i], fi8 = sh_dinv[i + 8] * sh_ca[i + 8];
        float s0 = sh_sc[m], s1 = sh_sc[m + 4];
        float a00 = ab[m * NN + i]           + ((i     == m)     ? 1.f : 0.f);
        float a01 = ab[m * NN + i + 8]       + ((i + 8 == m)     ? 1.f : 0.f);
        float a10 = ab[(m + 4) * NN + i]     + ((i     == m + 4) ? 1.f : 0.f);
        float a11 = ab[(m + 4) * NN + i + 8] + ((i + 8 == m + 4) ? 1.f : 0.f);
        float4 v = make_float4(tf32r(s0 * a00 * fi), tf32r(s0 * a01 * fi8),
                               tf32r(s1 * a10 * fi), tf32r(s1 * a11 * fi8));
        (s ? SAh : SAl)[(ib * 16 + ks) * 32 + ln] = v;
    }

    // ---- B-pack fills: adj -> B1, X[:,0:128) -> B2 ----
    for (int c = tid; c < 4096; c += 512){
        int ln = c & 31, ks = (c >> 5) & 15, jb = (c >> 9) & 3, hf = c >> 11;
        int gp = ln >> 2, tp = ln & 3;
        int j = jb * 32 + hf * 16 + gp, m = ks * 8 + tp;
        float4 v = make_float4(tf32r(ab[m * NN + j]),     tf32r(ab[(m + 4) * NN + j]),
                               tf32r(ab[m * NN + j + 8]), tf32r(ab[(m + 4) * NN + j + 8]));
        (hf ? B1h : B1l)[(jb * 16 + ks) * 32 + ln] = v;
        float4 w = make_float4(tf32r(xb[m * ND + j]),     tf32r(xb[(m + 4) * ND + j]),
                               tf32r(xb[m * ND + j + 8]), tf32r(xb[(m + 4) * ND + j + 8]));
        (hf ? B2h : B2l)[(jb * 16 + ks) * 32 + ln] = w;
    }
    __syncthreads();

    const uint4* pAl = (const uint4*)SAl + ibw * 512 + lane;
    const uint4* pAh = (const uint4*)SAh + ibw * 512 + lane;
    const uint4* p1l = (const uint4*)B1l + jbw * 512 + lane;
    const uint4* p1h = (const uint4*)B1h + jbw * 512 + lane;
    const uint4* p2l = (const uint4*)B2l + jbw * 512 + lane;
    const uint4* p2h = (const uint4*)B2h + jbw * 512 + lane;

    float cT[2][4][4], cX[2][4][4];

    // ====== Phase A: T1 = S^T adj  +  emb0 = S^T X0 (shared A) ======
    #pragma unroll
    for (int s = 0; s < 2; ++s)
        #pragma unroll
        for (int jt = 0; jt < 4; ++jt)
            #pragma unroll
            for (int q = 0; q < 4; ++q){ cT[s][jt][q] = 0.f; cX[s][jt][q] = 0.f; }

    #pragma unroll
    for (int ks = 0; ks < 16; ++ks){
        uint4 a0 = pAl[ks * 32], a1 = pAh[ks * 32];
        uint4 u  = p1l[ks * 32], v  = p1h[ks * 32];
        uint4 p  = p2l[ks * 32], q4 = p2h[ks * 32];
        MMA8S(cT[0][0], a0.x,a0.y,a0.z,a0.w, u.x, u.y);
        MMA8S(cX[0][0], a0.x,a0.y,a0.z,a0.w, p.x, p.y);
        MMA8S(cT[1][0], a1.x,a1.y,a1.z,a1.w, u.x, u.y);
        MMA8S(cX[1][0], a1.x,a1.y,a1.z,a1.w, p.x, p.y);
        MMA8S(cT[0][1], a0.x,a0.y,a0.z,a0.w, u.z, u.w);
        MMA8S(cX[0][1], a0.x,a0.y,a0.z,a0.w, p.z, p.w);
        MMA8S(cT[1][1], a1.x,a1.y,a1.z,a1.w, u.z, u.w);
        MMA8S(cX[1][1], a1.x,a1.y,a1.z,a1.w, p.z, p.w);
        MMA8S(cT[0][2], a0.x,a0.y,a0.z,a0.w, v.x, v.y);
        MMA8S(cX[0][2], a0.x,a0.y,a0.z,a0.w, q4.x, q4.y);
        MMA8S(cT[1][2], a1.x,a1.y,a1.z,a1.w, v.x, v.y);
        MMA8S(cX[1][2], a1.x,a1.y,a1.z,a1.w, q4.x, q4.y);
        MMA8S(cT[0][3], a0.x,a0.y,a0.z,a0.w, v.z, v.w);
        MMA8S(cX[0][3], a0.x,a0.y,a0.z,a0.w, q4.z, q4.w);
        MMA8S(cT[1][3], a1.x,a1.y,a1.z,a1.w, v.z, v.w);
        MMA8S(cX[1][3], a1.x,a1.y,a1.z,a1.w, q4.z, q4.w);
    }
    __syncthreads();   // phase A reads of B1/B2 complete

    // ---- emb tile 0 to gmem ----
    {
        float* eb = emb + (size_t)b * NN * ND;
        #pragma unroll
        for (int s = 0; s < 2; ++s)
            #pragma unroll
            for (int jt = 0; jt < 4; ++jt){
                int r0 = i0 + s * 16 + g, col = j0 + jt * 8 + 2 * tg;
                *(float2*)(eb + r0 * ND + col)       = make_float2(cX[s][jt][0], cX[s][jt][1]);
                *(float2*)(eb + (r0 + 8) * ND + col) = make_float2(cX[s][jt][2], cX[s][jt][3]);
            }
    }

    // ---- scatter T1 as T1^T (B-operand pack) into B1 buffer ----
    {
        float* B1f = (float*)B1l;   // hf=s selects +8192 floats (B1h)
        #pragma unroll
        for (int s = 0; s < 2; ++s)
            #pragma unroll
            for (int jt = 0; jt < 4; ++jt){
                int ks = jbw * 4 + jt;
                #pragma unroll
                for (int q = 0; q < 4; ++q){
                    int tp = (2 * tg + (q & 1)) & 3;
                    int mh = tg >> 1;
                    int comp = ((q >> 1) << 1) | mh;
                    B1f[s * 8192 + (((ibw * 16 + ks) * 32 + g * 4 + tp) << 2) + comp]
                        = tf32r(cT[s][jt][q]);
                }
            }
    }

    // ---- refill B2 with X[:,128:256) ----
    for (int c = tid; c < 4096; c += 512){
        int ln = c & 31, ks = (c >> 5) & 15, jb = (c >> 9) & 3, hf = c >> 11;
        int gp = ln >> 2, tp = ln & 3;
        int j = jb * 32 + hf * 16 + gp + 128, m = ks * 8 + tp;
        float4 w = make_float4(tf32r(xb[m * ND + j]),     tf32r(xb[(m + 4) * ND + j]),
                               tf32r(xb[m * ND + j + 8]), tf32r(xb[(m + 4) * ND + j + 8]));
        (hf ? B2h : B2l)[(jb * 16 + ks) * 32 + ln] = w;
    }
    __syncthreads();

    // ====== Phase B: nadj^T = S^T T1^T  +  emb1 = S^T X1 (shared A) ======
    #pragma unroll
    for (int s = 0; s < 2; ++s)
        #pragma unroll
        for (int jt = 0; jt < 4; ++jt)
            #pragma unroll
            for (int q = 0; q < 4; ++q){ cT[s][jt][q] = 0.f; cX[s][jt][q] = 0.f; }

    #pragma unroll
    for (int ks = 0; ks < 16; ++ks){
        uint4 a0 = pAl[ks * 32], a1 = pAh[ks * 32];
        uint4 u  = p1l[ks * 32], v  = p1h[ks * 32];
        uint4 p  = p2l[ks * 32], q4 = p2h[ks * 32];
        MMA8S(cT[0][0], a0.x,a0.y,a0.z,a0.w, u.x, u.y);
        MMA8S(cX[0][0], a0.x,a0.y,a0.z,a0.w, p.x, p.y);
        MMA8S(cT[1][0], a1.x,a1.y,a1.z,a1.w, u.x, u.y);
        MMA8S(cX[1][0], a1.x,a1.y,a1.z,a1.w, p.x, p.y);
        MMA8S(cT[0][1], a0.x,a0.y,a0.z,a0.w, u.z, u.w);
        MMA8S(cX[0][1], a0.x,a0.y,a0.z,a0.w, p.z, p.w);
        MMA8S(cT[1][1], a1.x,a1.y,a1.z,a1.w, u.z, u.w);
        MMA8S(cX[1][1], a1.x,a1.y,a1.z,a1.w, p.z, p.w);
        MMA8S(cT[0][2], a0.x,a0.y,a0.z,a0.w, v.x, v.y);
        MMA8S(cX[0][2], a0.x,a0.y,a0.z,a0.w, q4.x, q4.y);
        MMA8S(cT[1][2], a1.x,a1.y,a1.z,a1.w, v.x, v.y);
        MMA8S(cX[1][2], a1.x,a1.y,a1.z,a1.w, q4.x, q4.y);
        MMA8S(cT[0][3], a0.x,a0.y,a0.z,a0.w, v.z, v.w);
        MMA8S(cX[0][3], a0.x,a0.y,a0.z,a0.w, q4.z, q4.w);
        MMA8S(cT[1][3], a1.x,a1.y,a1.z,a1.w, v.z, v.w);
        MMA8S(cX[1][3], a1.x,a1.y,a1.z,a1.w, q4.z, q4.w);
    }

    // ---- epilogues: emb tile 1; nadj (transposed scatter) ----
    {
        float* eb = emb + (size_t)b * NN * ND + 128;
        float* nb = nadj + (size_t)b * NN * NN;
        #pragma unroll
        for (int s = 0; s < 2; ++s)
            #pragma unroll
            for (int jt = 0; jt < 4; ++jt){
                int r0 = i0 + s * 16 + g, col = j0 + jt * 8 + 2 * tg;
                *(float2*)(eb + r0 * ND + col)       = make_float2(cX[s][jt][0], cX[s][jt][1]);
                *(float2*)(eb + (r0 + 8) * ND + col) = make_float2(cX[s][jt][2], cX[s][jt][3]);
                // cT holds nadj^T: C'[r][c] = nadj[c][r]
                nb[col * NN + r0]           = cT[s][jt][0];
                nb[(col + 1) * NN + r0]     = cT[s][jt][1];
                nb[col * NN + r0 + 8]       = cT[s][jt][2];
                nb[(col + 1) * NN + r0 + 8] = cT[s][jt][3];
            }
    }
}

extern "C" void kernel_launch(void* const* d_in, const int* in_sizes, int n_in,
                              void* d_out, int out_size) {
    const float* x    = (const float*)d_in[0];
    const float* adj  = (const float*)d_in[1];
    const int*   head = (const int*)d_in[2];
    const float* lw   = (const float*)d_in[3];
    const float* bias = (const float*)d_in[4];

    float* out  = (float*)d_out;
    float* emb  = out;                            // [B, N, D]
    float* nadj = out + (size_t)NB * NN * ND;     // [B, N, N]

    const int dsmem = 12288 * 16;                 // 196,608 B (3 packs)
    cudaFuncSetAttribute(kmain, cudaFuncAttributeMaxDynamicSharedMemorySize, dsmem);
    kmain<<<NB, 512, dsmem>>>(x, adj, head, lw, bias, emb, nadj);
}

// round 9
// speedup vs baseline: 1.5095x; 1.2250x over previous
#include <cuda_runtime.h>
#include <cuda_fp16.h>
#include <cstdint>

#define NB 512
#define NN 128
#define ND 256
#define NTH 512

static __device__ __forceinline__ uint32_t h2(float lo, float hi){
    __half2 h = __floats2half2_rn(lo, hi);
    return *(uint32_t*)&h;
}

#define MMA16(C, A0,A1,A2,A3, B0, B1) \
    asm volatile("mma.sync.aligned.m16n8k16.row.col.f32.f16.f16.f32 " \
        "{%0,%1,%2,%3}, {%4,%5,%6,%7}, {%8,%9}, {%0,%1,%2,%3};" \
        : "+f"((C)[0]), "+f"((C)[1]), "+f"((C)[2]), "+f"((C)[3]) \
        : "r"(A0), "r"(A1), "r"(A2), "r"(A3), "r"(B0), "r"(B1))

// fp16 fragment packs, m16n8k16. lane = g*4+tg (g=lane>>2, tg=lane&3).
// A-chunk (ib, ks, lane; lo: s=0, hi: s=1): uint4 {a0,a1,a2,a3}
//   a0 = A[i][m0|m0+1], a1 = A[i+8][...], a2 = A[i][m0+8|m0+9], a3 = A[i+8][+8]
//   i = ib*32+s*16+g, m0 = ks*16+2*tg.
// B-chunk (jb, ks, lane; lo: jt0/1, hi: jt2/3): uint4 {b0_jA, b1_jA, b0_jB, b1_jB}
//   b0 = B[m0|m0+1][j], b1 = B[m0+8|m0+9][j]; jA = jb*32+hf*16+g, jB = jA+8.

__global__ __launch_bounds__(512, 1) void kmain(
    const float* __restrict__ x, const float* __restrict__ adj,
    const int* __restrict__ head, const float* __restrict__ lw,
    const float* __restrict__ bias, float* __restrict__ emb, float* __restrict__ nadj)
{
    extern __shared__ uint4 smq[];
    uint4* SAl = smq;            // 16 KB each
    uint4* SAh = smq + 1024;
    uint4* B1l = smq + 2048;     // adj -> T1^T
    uint4* B1h = smq + 3072;
    uint4* B2l = smq + 4096;     // X0 -> X1
    uint4* B2h = smq + 5120;
    float* stage = (float*)(smq + 6144);   // nadj staging, 128 x pitch132 fp32

    __shared__ float sh_w[ND];
    __shared__ float sh_dinv[NN], sh_coef[NN], sh_dv[NN], sh_alpha[NN], sh_ca[NN], sh_sc[NN];
    __shared__ int   sh_flags[NN];
    __shared__ float sh_cut;

    const int b = blockIdx.x, tid = threadIdx.x;
    const int lane = tid & 31, wid = tid >> 5;
    const int g = lane >> 2, tg = lane & 3;
    const int ibw = wid >> 2, jbw = wid & 3;
    const int i0 = ibw * 32, j0 = jbw * 32;

    const float* xb = x + (size_t)b * NN * ND;
    const float* ab = adj + (size_t)b * NN * NN;

    if (tid < ND) sh_w[tid] = lw[tid];
    if (tid < NN) sh_flags[tid] = 0;
    if (tid == 0) sh_cut = 0.f;
    __syncthreads();

    sh_flags[head[(size_t)b * NTH + tid] & (NN - 1)] = 1;

    // ---- rowsum_r, v_r = x[r]·w (fp32, from gmem) ----
    for (int r = wid; r < NN; r += 16){
        float s = 0.f, rs = 0.f;
        #pragma unroll
        for (int q = 0; q < 8; ++q) s += xb[r * ND + lane + q * 32] * sh_w[lane + q * 32];
        #pragma unroll
        for (int q = 0; q < 4; ++q) rs += ab[r * NN + lane + q * 32];
        #pragma unroll
        for (int o = 16; o; o >>= 1){
            s  += __shfl_down_sync(~0u, s, o);
            rs += __shfl_down_sync(~0u, rs, o);
        }
        if (!lane){
            float di = rsqrtf(fmaxf(rs + 1.f, 1.f));
            sh_dinv[r] = di;
            sh_coef[r] = (rs > 0.f) ? di : 0.f;
            sh_dv[r]   = di * s;
        }
    }
    __syncthreads();

    // ---- alpha ----
    const float bia = bias[0];
    for (int r = wid; r < NN; r += 16){
        float t = 0.f;
        #pragma unroll
        for (int q = 0; q < 4; ++q){
            int m = lane + q * 32;
            t += ab[r * NN + m] * sh_dv[m];
        }
        #pragma unroll
        for (int o = 16; o; o >>= 1) t += __shfl_down_sync(~0u, t, o);
        if (!lane){
            t += sh_dv[r];
            float o1 = sh_coef[r] * t + bia;
            sh_alpha[r] = 1.f / (1.f + __expf(-(o1 * o1)));
        }
    }
    const int nuniq = __syncthreads_count((tid < NN) ? sh_flags[tid] : 0);

    // ---- cut (k-th largest, tie-correct) ----
    if (nuniq > 1 && tid < NN){
        float a = sh_alpha[tid];
        int gt = 0, ge = 0;
        for (int j2 = 0; j2 < NN; ++j2){
            float aj = sh_alpha[j2];
            gt += (aj > a); ge += (aj >= a);
        }
        int k   = (nuniq + 9) / 10 + 1;
        int idx = min(k - 1, NN - 1);
        if (gt <= idx && idx < ge) sh_cut = a;
    }
    __syncthreads();
    if (tid < NN) sh_ca[tid] = fmaxf(sh_alpha[tid] + 1e-7f - sh_cut, 0.f);
    __syncthreads();

    // ---- sc_m = coef_m / max(coef_m * sum_j (adj+I)_mj dinv_j ca_j, eps) ----
    for (int m = wid; m < NN; m += 16){
        float ss = 0.f;
        #pragma unroll
        for (int q = 0; q < 4; ++q){
            int j = lane + q * 32;
            float a = ab[m * NN + j] + ((j == m) ? 1.f : 0.f);
            ss += a * sh_dinv[j] * sh_ca[j];
        }
        #pragma unroll
        for (int o = 16; o; o >>= 1) ss += __shfl_down_sync(~0u, ss, o);
        if (!lane){
            float c = sh_coef[m];
            sh_sc[m] = c / fmaxf(c * ss, 1e-12f);
        }
    }
    __syncthreads();

    // ---- A-pack fill: S^T (fp16 fragment order) ----
    for (int c = tid; c < 2048; c += 512){
        int ln = c & 31, ks = (c >> 5) & 7, ib = (c >> 8) & 3, sf = (c >> 10) & 1;
        int gp = ln >> 2, tp = ln & 3;
        int i = ib * 32 + sf * 16 + gp;
        int m0 = ks * 16 + 2 * tp;
        float fi  = sh_dinv[i] * sh_ca[i], fi8 = sh_dinv[i + 8] * sh_ca[i + 8];
        float s0 = sh_sc[m0], s1 = sh_sc[m0 + 1], s8 = sh_sc[m0 + 8], s9 = sh_sc[m0 + 9];
        uint32_t a0 = h2(s0 * (ab[m0 * NN + i]       + (i == m0))       * fi,
                         s1 * (ab[(m0 + 1) * NN + i] + (i == m0 + 1))   * fi);
        uint32_t a1 = h2(s0 * (ab[m0 * NN + i + 8]       + (i + 8 == m0))     * fi8,
                         s1 * (ab[(m0 + 1) * NN + i + 8] + (i + 8 == m0 + 1)) * fi8);
        uint32_t a2 = h2(s8 * (ab[(m0 + 8) * NN + i] + (i == m0 + 8)) * fi,
                         s9 * (ab[(m0 + 9) * NN + i] + (i == m0 + 9)) * fi);
        uint32_t a3 = h2(s8 * (ab[(m0 + 8) * NN + i + 8] + (i + 8 == m0 + 8)) * fi8,
                         s9 * (ab[(m0 + 9) * NN + i + 8] + (i + 8 == m0 + 9)) * fi8);
        (sf ? SAh : SAl)[(ib * 8 + ks) * 32 + ln] = make_uint4(a0, a1, a2, a3);
    }

    // ---- B-pack fills: adj -> B1, X[:,0:128) -> B2 ----
    for (int c = tid; c < 2048; c += 512){
        int ln = c & 31, ks = (c >> 5) & 7, jb = (c >> 8) & 3, hf = (c >> 10) & 1;
        int gp = ln >> 2, tp = ln & 3;
        int m0 = ks * 16 + 2 * tp;
        int jA = jb * 32 + hf * 16 + gp, jB = jA + 8;
        (hf ? B1h : B1l)[(jb * 8 + ks) * 32 + ln] = make_uint4(
            h2(ab[m0 * NN + jA], ab[(m0 + 1) * NN + jA]),
            h2(ab[(m0 + 8) * NN + jA], ab[(m0 + 9) * NN + jA]),
            h2(ab[m0 * NN + jB], ab[(m0 + 1) * NN + jB]),
            h2(ab[(m0 + 8) * NN + jB], ab[(m0 + 9) * NN + jB]));
        (hf ? B2h : B2l)[(jb * 8 + ks) * 32 + ln] = make_uint4(
            h2(xb[m0 * ND + jA], xb[(m0 + 1) * ND + jA]),
            h2(xb[(m0 + 8) * ND + jA], xb[(m0 + 9) * ND + jA]),
            h2(xb[m0 * ND + jB], xb[(m0 + 1) * ND + jB]),
            h2(xb[(m0 + 8) * ND + jB], xb[(m0 + 9) * ND + jB]));
    }
    __syncthreads();

    const uint4* pAl = SAl + ibw * 256 + lane;
    const uint4* pAh = SAh + ibw * 256 + lane;
    const uint4* p1l = B1l + jbw * 256 + lane;
    const uint4* p1h = B1h + jbw * 256 + lane;
    const uint4* p2l = B2l + jbw * 256 + lane;
    const uint4* p2h = B2h + jbw * 256 + lane;

    float cT[2][4][4], cX[2][4][4];

    // ====== Phase A: T1 = S^T adj + emb0 = S^T X0 (shared A) ======
    #pragma unroll
    for (int s = 0; s < 2; ++s)
        #pragma unroll
        for (int jt = 0; jt < 4; ++jt)
            #pragma unroll
            for (int q = 0; q < 4; ++q){ cT[s][jt][q] = 0.f; cX[s][jt][q] = 0.f; }

    #pragma unroll
    for (int ks = 0; ks < 8; ++ks){
        uint4 a0 = pAl[ks * 32], a1 = pAh[ks * 32];
        uint4 u  = p1l[ks * 32], v  = p1h[ks * 32];
        uint4 p  = p2l[ks * 32], q4 = p2h[ks * 32];
        MMA16(cT[0][0], a0.x,a0.y,a0.z,a0.w, u.x, u.y);
        MMA16(cX[0][0], a0.x,a0.y,a0.z,a0.w, p.x, p.y);
        MMA16(cT[1][0], a1.x,a1.y,a1.z,a1.w, u.x, u.y);
        MMA16(cX[1][0], a1.x,a1.y,a1.z,a1.w, p.x, p.y);
        MMA16(cT[0][1], a0.x,a0.y,a0.z,a0.w, u.z, u.w);
        MMA16(cX[0][1], a0.x,a0.y,a0.z,a0.w, p.z, p.w);
        MMA16(cT[1][1], a1.x,a1.y,a1.z,a1.w, u.z, u.w);
        MMA16(cX[1][1], a1.x,a1.y,a1.z,a1.w, p.z, p.w);
        MMA16(cT[0][2], a0.x,a0.y,a0.z,a0.w, v.x, v.y);
        MMA16(cX[0][2], a0.x,a0.y,a0.z,a0.w, q4.x, q4.y);
        MMA16(cT[1][2], a1.x,a1.y,a1.z,a1.w, v.x, v.y);
        MMA16(cX[1][2], a1.x,a1.y,a1.z,a1.w, q4.x, q4.y);
        MMA16(cT[0][3], a0.x,a0.y,a0.z,a0.w, v.z, v.w);
        MMA16(cX[0][3], a0.x,a0.y,a0.z,a0.w, q4.z, q4.w);
        MMA16(cT[1][3], a1.x,a1.y,a1.z,a1.w, v.z, v.w);
        MMA16(cX[1][3], a1.x,a1.y,a1.z,a1.w, q4.z, q4.w);
    }
    __syncthreads();   // phase A reads of B1/B2 complete

    // ---- emb tile 0 ----
    {
        float* eb = emb + (size_t)b * NN * ND;
        #pragma unroll
        for (int s = 0; s < 2; ++s)
            #pragma unroll
            for (int jt = 0; jt < 4; ++jt){
                int r0 = i0 + s * 16 + g, col = j0 + jt * 8 + 2 * tg;
                *(float2*)(eb + r0 * ND + col)       = make_float2(cX[s][jt][0], cX[s][jt][1]);
                *(float2*)(eb + (r0 + 8) * ND + col) = make_float2(cX[s][jt][2], cX[s][jt][3]);
            }
    }

    // ---- scatter T1 as T1^T (B-pack) into B1 ----
    {
        uint32_t* B1u = (uint32_t*)B1l;   // B1h contiguous at +4096 u32
        #pragma unroll
        for (int s = 0; s < 2; ++s)
            #pragma unroll
            for (int jt = 0; jt < 4; ++jt){
                int c0 = j0 + jt * 8 + 2 * tg;
                int ksn = c0 >> 4, rem = c0 & 15;
                int mh = rem >> 3, tp = (rem & 7) >> 1;
                #pragma unroll
                for (int rs = 0; rs < 2; ++rs){
                    int rr = i0 + s * 16 + g + rs * 8;
                    uint32_t val = h2(cT[s][jt][rs * 2], cT[s][jt][rs * 2 + 1]);
                    int jb = rr >> 5, jtp = (rr >> 3) & 3, gg = rr & 7;
                    int lidx = (((jb * 8 + ksn) * 32 + gg * 4 + tp) << 2) + (jtp & 1) * 2 + mh;
                    B1u[(jtp >> 1) * 4096 + lidx] = val;
                }
            }
    }

    // ---- refill B2 with X[:,128:256) ----
    for (int c = tid; c < 2048; c += 512){
        int ln = c & 31, ks = (c >> 5) & 7, jb = (c >> 8) & 3, hf = (c >> 10) & 1;
        int gp = ln >> 2, tp = ln & 3;
        int m0 = ks * 16 + 2 * tp;
        int jA = jb * 32 + hf * 16 + gp + 128, jB = jA + 8;
        (hf ? B2h : B2l)[(jb * 8 + ks) * 32 + ln] = make_uint4(
            h2(xb[m0 * ND + jA], xb[(m0 + 1) * ND + jA]),
            h2(xb[(m0 + 8) * ND + jA], xb[(m0 + 9) * ND + jA]),
            h2(xb[m0 * ND + jB], xb[(m0 + 1) * ND + jB]),
            h2(xb[(m0 + 8) * ND + jB], xb[(m0 + 9) * ND + jB]));
    }
    __syncthreads();

    // ====== Phase B: nadj^T = S^T T1^T + emb1 = S^T X1 (shared A) ======
    #pragma unroll
    for (int s = 0; s < 2; ++s)
        #pragma unroll
        for (int jt = 0; jt < 4; ++jt)
            #pragma unroll
            for (int q = 0; q < 4; ++q){ cT[s][jt][q] = 0.f; cX[s][jt][q] = 0.f; }

    #pragma unroll
    for (int ks = 0; ks < 8; ++ks){
        uint4 a0 = pAl[ks * 32], a1 = pAh[ks * 32];
        uint4 u  = p1l[ks * 32], v  = p1h[ks * 32];
        uint4 p  = p2l[ks * 32], q4 = p2h[ks * 32];
        MMA16(cT[0][0], a0.x,a0.y,a0.z,a0.w, u.x, u.y);
        MMA16(cX[0][0], a0.x,a0.y,a0.z,a0.w, p.x, p.y);
        MMA16(cT[1][0], a1.x,a1.y,a1.z,a1.w, u.x, u.y);
        MMA16(cX[1][0], a1.x,a1.y,a1.z,a1.w, p.x, p.y);
        MMA16(cT[0][1], a0.x,a0.y,a0.z,a0.w, u.z, u.w);
        MMA16(cX[0][1], a0.x,a0.y,a0.z,a0.w, p.z, p.w);
        MMA16(cT[1][1], a1.x,a1.y,a1.z,a1.w, u.z, u.w);
        MMA16(cX[1][1], a1.x,a1.y,a1.z,a1.w, p.z, p.w);
        MMA16(cT[0][2], a0.x,a0.y,a0.z,a0.w, v.x, v.y);
        MMA16(cX[0][2], a0.x,a0.y,a0.z,a0.w, q4.x, q4.y);
        MMA16(cT[1][2], a1.x,a1.y,a1.z,a1.w, v.x, v.y);
        MMA16(cX[1][2], a1.x,a1.y,a1.z,a1.w, q4.x, q4.y);
        MMA16(cT[0][3], a0.x,a0.y,a0.z,a0.w, v.z, v.w);
        MMA16(cX[0][3], a0.x,a0.y,a0.z,a0.w, q4.z, q4.w);
        MMA16(cT[1][3], a1.x,a1.y,a1.z,a1.w, v.z, v.w);
        MMA16(cX[1][3], a1.x,a1.y,a1.z,a1.w, q4.z, q4.w);
    }

    // ---- emb tile 1 (direct) ----
    {
        float* eb = emb + (size_t)b * NN * ND + 128;
        #pragma unroll
        for (int s = 0; s < 2; ++s)
            #pragma unroll
            for (int jt = 0; jt < 4; ++jt){
                int r0 = i0 + s * 16 + g, col = j0 + jt * 8 + 2 * tg;
                *(float2*)(eb + r0 * ND + col)       = make_float2(cX[s][jt][0], cX[s][jt][1]);
                *(float2*)(eb + (r0 + 8) * ND + col) = make_float2(cX[s][jt][2], cX[s][jt][3]);
            }
    }

    // ---- nadj: stage transpose in smem (conflict-free), then coalesced store ----
    #pragma unroll
    for (int s = 0; s < 2; ++s)
        #pragma unroll
        for (int jt = 0; jt < 4; ++jt)
            #pragma unroll
            for (int q = 0; q < 4; ++q){
                int col = j0 + jt * 8 + 2 * tg + (q & 1);
                int row = i0 + s * 16 + g + ((q >> 1) * 8);
                stage[col * 132 + row] = cT[s][jt][q];   // stage[a][b] = nadj[a][b]
            }
    __syncthreads();
    {
        float* nb = nadj + (size_t)b * NN * NN;
        for (int idx = tid; idx < 4096; idx += 512){
            int a = idx >> 5, bq = (idx & 31) * 4;
            *(float4*)(nb + a * NN + bq) = *(const float4*)(stage + a * 132 + bq);
        }
    }
}

extern "C" void kernel_launch(void* const* d_in, const int* in_sizes, int n_in,
                              void* d_out, int out_size) {
    const float* x    = (const float*)d_in[0];
    const float* adj  = (const float*)d_in[1];
    const int*   head = (const int*)d_in[2];
    const float* lw   = (const float*)d_in[3];
    const float* bias = (const float*)d_in[4];

    float* out  = (float*)d_out;
    float* emb  = out;                            // [B, N, D]
    float* nadj = out + (size_t)NB * NN * ND;     // [B, N, N]

    const int dsmem = 6144 * 16 + 128 * 132 * 4;  // 98304 + 67584 = 165,888 B
    cudaFuncSetAttribute(kmain, cudaFuncAttributeMaxDynamicSharedMemorySize, dsmem);
    kmain<<<NB, 512, dsmem>>>(x, adj, head, lw, bias, emb, nadj);
}